// round 6
// baseline (speedup 1.0000x reference)
#include <cuda_runtime.h>

// GridPooling: scatter-max of point features into a 32x32x32 voxel grid.
// features: [N, 128] f32 ; points: [N, 3] f32 in [0,1)
// out: [32768, 128] f32, = max(segment_max(features, cell), 0), empty cells 0.
//
// Strategy: zero-init output, then signed-int atomicMax on the float bit
// pattern. For floats >= 0 the int ordering matches float ordering, and
// negative floats reinterpret as negative ints, so they can never beat the
// zero init -- which is exactly the reference semantics (maximum(pooled, 0)).
// Non-positive values therefore need no atomic at all (~50% of N(0,1) data).

#define GRID_DIM 32
#define FEAT 128

__global__ __launch_bounds__(256)
void grid_pool_scatter_kernel(const float* __restrict__ feats,
                              const float* __restrict__ pts,
                              int* __restrict__ out,
                              int n_points)
{
    const int gtid = blockIdx.x * blockDim.x + threadIdx.x;
    const int p    = gtid >> 5;          // one warp per point
    const int lane = threadIdx.x & 31;
    if (p >= n_points) return;

    // Lane 0 computes the flat cell id, broadcast to the warp.
    int cell = 0;
    if (lane == 0) {
        const float x = pts[3 * p + 0];
        const float y = pts[3 * p + 1];
        const float z = pts[3 * p + 2];
        int ix = __float2int_rd(x * (float)GRID_DIM);
        int iy = __float2int_rd(y * (float)GRID_DIM);
        int iz = __float2int_rd(z * (float)GRID_DIM);
        ix = min(max(ix, 0), GRID_DIM - 1);
        iy = min(max(iy, 0), GRID_DIM - 1);
        iz = min(max(iz, 0), GRID_DIM - 1);
        cell = ix * (GRID_DIM * GRID_DIM) + iy * GRID_DIM + iz;
    }
    cell = __shfl_sync(0xffffffffu, cell, 0);

    // Each lane handles 4 consecutive features: warp covers the 512B row.
    const float4 v =
        reinterpret_cast<const float4*>(feats)[p * (FEAT / 4) + lane];

    int* o = out + cell * FEAT + lane * 4;
    // Fire-and-forget RED.MAX.S32; skip values that cannot beat the 0 init.
    if (v.x > 0.0f) atomicMax(o + 0, __float_as_int(v.x));
    if (v.y > 0.0f) atomicMax(o + 1, __float_as_int(v.y));
    if (v.z > 0.0f) atomicMax(o + 2, __float_as_int(v.z));
    if (v.w > 0.0f) atomicMax(o + 3, __float_as_int(v.w));
}

extern "C" void kernel_launch(void* const* d_in, const int* in_sizes, int n_in,
                              void* d_out, int out_size)
{
    const float* feats = (const float*)d_in[0];   // [N, 128]
    const float* pts   = (const float*)d_in[1];   // [N, 3]
    int* out           = (int*)d_out;             // [32768, 128] f32 bits

    const int n_points = in_sizes[1] / 3;

    // Zero-init output (graph-capturable memset node).
    cudaMemsetAsync(d_out, 0, (size_t)out_size * sizeof(float), 0);

    const int threads = 256;
    const int warps_needed = n_points;             // one warp per point
    const int blocks = (warps_needed * 32 + threads - 1) / threads;
    grid_pool_scatter_kernel<<<blocks, threads>>>(feats, pts, out, n_points);
}